// round 5
// baseline (speedup 1.0000x reference)
#include <cuda_runtime.h>
#include <cstdint>

#define SEQ   2048
#define BATCH 64
#define DIN   128
#define DH    256
#define G3    (3*DH)   // 768

#define NG    16       // batch groups
#define NP    8        // producer blocks (unit tiles) per group
#define BPG   4        // batches per group
#define UPB   32       // hidden units per block
#define ROWSB 96       // 3*UPB gate rows per block
#define HPAD  260

// ---------------- scratch (device globals) ----------------
__device__ float g_gi[(size_t)SEQ * BATCH * G3];
__device__ float g_outs[(size_t)SEQ * BATCH * DH];
__device__ float g_h[2][BATCH * DH];
__device__ float g_scorep[(size_t)SEQ * BATCH * NP];
__device__ float g_scores[SEQ * BATCH];
__device__ float g_wpart[8 * BATCH * DH];
__device__ unsigned int g_flag[NG * NP];    // [m*8+ut] = steps completed

// ---------------- helpers ----------------
__device__ __forceinline__ void fma2(unsigned long long& acc,
                                     unsigned long long a,
                                     unsigned long long b) {
    asm volatile("fma.rn.f32x2 %0, %1, %2, %0;" : "+l"(acc) : "l"(a), "l"(b));
}
__device__ __forceinline__ float2 u2f2(unsigned long long v) {
    float2 f;
    asm("mov.b64 {%0, %1}, %2;" : "=f"(f.x), "=f"(f.y) : "l"(v));
    return f;
}
__device__ __forceinline__ unsigned ld_acq(const unsigned* p) {
    unsigned v;
    asm volatile("ld.global.acquire.gpu.u32 %0, [%1];" : "=r"(v) : "l"(p) : "memory");
    return v;
}
__device__ __forceinline__ void st_rel(unsigned* p, unsigned v) {
    asm volatile("st.global.release.gpu.u32 [%0], %1;" :: "l"(p), "r"(v) : "memory");
}

__global__ void k_init() {
    g_flag[threadIdx.x] = 0u;   // 128 threads
}

// ---------------- Phase 1: GI = mask(data) @ W_ih^T + b_ih ----------------
__global__ void __launch_bounds__(256, 1) gi_gemm(const float* __restrict__ X,
                                                  const float* __restrict__ Wih,
                                                  const float* __restrict__ bih) {
    extern __shared__ float sm[];
    float* As = sm;                // 128 x 132
    float* Bs = sm + 128 * 132;    // 128 x 132
    __shared__ unsigned char maskf[128];

    const int tid = threadIdx.x;
    const int n0 = blockIdx.x * 128;
    const int m0 = blockIdx.y * 128;

    if (tid < 128) maskf[tid] = (X[(size_t)(m0 + tid) * DIN + 127] > 0.0f) ? 1 : 0;
    __syncthreads();

#pragma unroll
    for (int it = 0; it < 16; it++) {
        int t = tid + it * 256;
        int r = t >> 5, kk = t & 31;
        float4 va = *(const float4*)&X[(size_t)(m0 + r) * DIN + kk * 4];
        if (maskf[r] && kk >= 8 && kk < 16) va = make_float4(0.f, 0.f, 0.f, 0.f);
        *(float4*)&As[r * 132 + kk * 4] = va;
        float4 vb = *(const float4*)&Wih[(size_t)(n0 + r) * DIN + kk * 4];
        *(float4*)&Bs[r * 132 + kk * 4] = vb;
    }
    __syncthreads();

    const int tx = tid & 15;
    const int ty = tid >> 4;

    unsigned long long acc[8][8];
#pragma unroll
    for (int i = 0; i < 8; i++)
#pragma unroll
        for (int j = 0; j < 8; j++) acc[i][j] = 0ull;

#pragma unroll 8
    for (int p = 0; p < 64; p++) {
        unsigned long long av[8], bv[8];
#pragma unroll
        for (int i = 0; i < 8; i++)
            av[i] = *(const unsigned long long*)&As[(ty + 16 * i) * 132 + 2 * p];
#pragma unroll
        for (int j = 0; j < 8; j++)
            bv[j] = *(const unsigned long long*)&Bs[(tx + 16 * j) * 132 + 2 * p];
#pragma unroll
        for (int i = 0; i < 8; i++)
#pragma unroll
            for (int j = 0; j < 8; j++) fma2(acc[i][j], av[i], bv[j]);
    }

    __syncthreads();
#pragma unroll
    for (int i = 0; i < 8; i++)
#pragma unroll
        for (int j = 0; j < 8; j++) {
            float2 f = u2f2(acc[i][j]);
            As[(ty + 16 * i) * 132 + tx + 16 * j] = f.x + f.y;
        }
    __syncthreads();

#pragma unroll
    for (int it = 0; it < 16; it++) {
        int t = tid + it * 256;
        int r = t >> 5, kk = t & 31;
        float4 c = *(const float4*)&As[r * 132 + kk * 4];
        float4 b = *(const float4*)&bih[n0 + kk * 4];
        c.x += b.x; c.y += b.y; c.z += b.z; c.w += b.w;
        *(float4*)&g_gi[(size_t)(m0 + r) * G3 + n0 + kk * 4] = c;
    }
}

// ---------------- Phase 2: persistent GRU recurrence ----------------
// 128 blocks = 16 batch-groups x 8 unit-tiles. W_hh in REGISTERS (per-thread,
// loaded once). h exchanged via L2 with per-producer release flags; each
// consumer thread acquires exactly the flag of the slice it stages.
__global__ void __launch_bounds__(256, 1) gru_rec(const float* __restrict__ Whh,
                                                  const float* __restrict__ bhh_g,
                                                  const float* __restrict__ watt) {
    extern __shared__ float sm[];
    float* h_sh = sm;                    // 4 x 260
    float* part = sm + BPG * HPAD;       // 384 x 9

    const int tid = threadIdx.x;
    const int ut  = blockIdx.x & 7;      // unit tile 0..7
    const int m   = blockIdx.x >> 3;     // group 0..15

    const int kc = tid >> 4;             // 0..15 k-chunk
    const int rq = tid & 15;             // row group
    const int kbase = kc * 16;

    // epilogue identity (tid < 128)
    const int eb = tid >> 5;             // batch 0..3
    const int eu = tid & 31;             // unit 0..31
    const int ug = ut * UPB + eu;
    const int bg = m * BPG + eb;

    // ---- W_hh tile into registers: 6 rows (rq+16j) x 16 k (kc chunk) ----
    ulonglong2 Wr[6][4];
#pragma unroll
    for (int j = 0; j < 6; j++) {
        const int r = rq + 16 * j;                  // local row 0..95
        const int g = r >> 5, uu = r & 31;
        const float* src = &Whh[(size_t)(g * DH + ut * UPB + uu) * DH + kbase];
#pragma unroll
        for (int q = 0; q < 4; q++)
            Wr[j][q] = *(const ulonglong2*)&src[q * 4];
    }

    float bhh0 = 0.f, bhh1 = 0.f, bhh2 = 0.f, wattv = 0.f;
    if (tid < 128) {
        bhh0 = bhh_g[0 * DH + ug];
        bhh1 = bhh_g[1 * DH + ug];
        bhh2 = bhh_g[2 * DH + ug];
        wattv = watt[ug];
    }

    // staging identity: thread stages one float4 of h; its producer:
    const int sb = tid >> 6;             // batch 0..3
    const int sf = tid & 63;             // float4 index 0..63 (k = sf*4)
    const unsigned* myflag = &g_flag[m * NP + ((tid >> 3) & 7)];   // = sf>>3

    for (int s = 0; s < SEQ; s++) {
        // prefetch gi (independent of h) — issued before the spin
        float gir = 0.f, giz = 0.f, gin = 0.f;
        if (tid < 128) {
            const size_t base = ((size_t)s * BATCH + bg) * G3 + ug;
            gir = __ldcg(&g_gi[base]);
            giz = __ldcg(&g_gi[base + DH]);
            gin = __ldcg(&g_gi[base + 2 * DH]);
        }

        // wait for my producer (converged warp vote), stage my float4
        if (s > 0) {
            const unsigned tgt = (unsigned)s;
            unsigned v;
            do { v = ld_acq(myflag); } while (!__all_sync(0xffffffffu, v >= tgt));
            float4 hv = __ldcg((const float4*)&g_h[(s - 1) & 1][(m * BPG + sb) * DH + sf * 4]);
            *(float4*)&h_sh[sb * HPAD + sf * 4] = hv;
        } else {
            *(float4*)&h_sh[sb * HPAD + sf * 4] = make_float4(0.f, 0.f, 0.f, 0.f);
        }
        __syncthreads();

        // dots: 4 batches x 6 rows x 16 k, W in regs, h broadcast LDS
        unsigned long long acc[4][6];
#pragma unroll
        for (int i = 0; i < 4; i++)
#pragma unroll
            for (int j = 0; j < 6; j++) acc[i][j] = 0ull;

#pragma unroll
        for (int q = 0; q < 4; q++) {
            ulonglong2 hq[4];
#pragma unroll
            for (int i = 0; i < 4; i++)
                hq[i] = *(const ulonglong2*)&h_sh[i * HPAD + kbase + q * 4];
#pragma unroll
            for (int i = 0; i < 4; i++)
#pragma unroll
                for (int j = 0; j < 6; j++) {
                    fma2(acc[i][j], hq[i].x, Wr[j][q].x);
                    fma2(acc[i][j], hq[i].y, Wr[j][q].y);
                }
        }

        // kc-pair shuffle pre-reduce, then STS (kc-even threads only)
#pragma unroll
        for (int i = 0; i < 4; i++)
#pragma unroll
            for (int j = 0; j < 6; j++) {
                float2 f = u2f2(acc[i][j]);
                float v = f.x + f.y;
                v += __shfl_xor_sync(0xffffffffu, v, 16);
                if ((tid & 16) == 0)
                    part[(i * ROWSB + rq + 16 * j) * 9 + (kc >> 1)] = v;
            }
        __syncthreads();

        float hnew = 0.f;
        if (tid < 128) {
            float Ar = bhh0 + gir, Az = bhh1 + giz, An = bhh2;
            const int o_r = (eb * ROWSB + eu) * 9;
            const int o_z = (eb * ROWSB + UPB + eu) * 9;
            const int o_n = (eb * ROWSB + 2 * UPB + eu) * 9;
#pragma unroll
            for (int c = 0; c < 8; c++) {
                Ar += part[o_r + c];
                Az += part[o_z + c];
                An += part[o_n + c];
            }
            const float rr = 1.0f / (1.0f + __expf(-Ar));
            const float zz = 1.0f / (1.0f + __expf(-Az));
            const float nn = tanhf(fmaf(rr, An, gin));
            const float hold = h_sh[eb * HPAD + ug];
            hnew = fmaf(zz, hold - nn, nn);
            __stcg(&g_h[s & 1][bg * DH + ug], hnew);
        }
        __syncthreads();   // h stores issued; part reads done

        if (tid == 0) st_rel(&g_flag[m * NP + ut], (unsigned)(s + 1));

        // tail work off the inter-block critical path
        if (tid < 128) {
            g_outs[((size_t)s * BATCH + bg) * DH + ug] = hnew;
            float sc = hnew * wattv;
#pragma unroll
            for (int o = 16; o > 0; o >>= 1) sc += __shfl_xor_sync(0xffffffffu, sc, o);
            if (eu == 0) g_scorep[((size_t)s * BATCH + bg) * NP + ut] = sc;
        }
    }
}

// ---------------- Phase 3: attention ----------------
__global__ void k_scores_red() {
    const int idx = blockIdx.x * 256 + threadIdx.x;
    const float4* p = (const float4*)&g_scorep[(size_t)idx * NP];
    float4 a = p[0], b = p[1];
    g_scores[idx] = (a.x + a.y + a.z + a.w) + (b.x + b.y + b.z + b.w);
}

__global__ void k_softmax() {
    __shared__ float red[256];
    const int b = blockIdx.x, tid = threadIdx.x;
    float mx = -1e30f;
    for (int s = tid; s < SEQ; s += 256) mx = fmaxf(mx, g_scores[s * BATCH + b]);
    red[tid] = mx; __syncthreads();
    for (int o = 128; o > 0; o >>= 1) { if (tid < o) red[tid] = fmaxf(red[tid], red[tid + o]); __syncthreads(); }
    mx = red[0]; __syncthreads();
    float sum = 0.f;
    for (int s = tid; s < SEQ; s += 256) sum += __expf(g_scores[s * BATCH + b] - mx);
    red[tid] = sum; __syncthreads();
    for (int o = 128; o > 0; o >>= 1) { if (tid < o) red[tid] += red[tid + o]; __syncthreads(); }
    const float inv = 1.0f / red[0];
    for (int s = tid; s < SEQ; s += 256)
        g_scores[s * BATCH + b] = __expf(g_scores[s * BATCH + b] - mx) * inv;
}

__global__ void k_wsum1() {
    const int b = blockIdx.x, c = blockIdx.y, h = threadIdx.x;
    float acc = 0.f;
    const int s0 = c * 256;
#pragma unroll 4
    for (int s = s0; s < s0 + 256; s++)
        acc = fmaf(__ldg(&g_scores[s * BATCH + b]),
                   g_outs[((size_t)s * BATCH + b) * DH + h], acc);
    g_wpart[(c * BATCH + b) * DH + h] = acc;
}

__global__ void k_wsum2(float* __restrict__ out) {
    const int b = blockIdx.x, h = threadIdx.x;
    float acc = 0.f;
#pragma unroll
    for (int c = 0; c < 8; c++) acc += g_wpart[(c * BATCH + b) * DH + h];
    out[b * DH + h] = acc;
}

// ---------------- launch ----------------
extern "C" void kernel_launch(void* const* d_in, const int* in_sizes, int n_in,
                              void* d_out, int out_size) {
    const float* data = (const float*)d_in[0];
    const float* Wih  = (const float*)d_in[1];
    const float* Whh  = (const float*)d_in[2];
    const float* bih  = (const float*)d_in[3];
    const float* bhh  = (const float*)d_in[4];
    const float* watt = (const float*)d_in[5];
    float* out = (float*)d_out;

    const int gi_smem  = 2 * 128 * 132 * (int)sizeof(float);                 // 135168
    const int gru_smem = (BPG * HPAD + 384 * 9) * (int)sizeof(float);        // 17984

    cudaFuncSetAttribute(gi_gemm, cudaFuncAttributeMaxDynamicSharedMemorySize, gi_smem);
    cudaFuncSetAttribute(gru_rec, cudaFuncAttributeMaxDynamicSharedMemorySize, gru_smem);

    k_init<<<1, 128>>>();
    dim3 gg(G3 / 128, (SEQ * BATCH) / 128);   // (6, 1024)
    gi_gemm<<<gg, 256, gi_smem>>>(data, Wih, bih);
    gru_rec<<<NG * NP, 256, gru_smem>>>(Whh, bhh, watt);
    k_scores_red<<<(SEQ * BATCH) / 256, 256>>>();
    k_softmax<<<BATCH, 256>>>();
    dim3 gw(BATCH, 8);
    k_wsum1<<<gw, 256>>>();
    k_wsum2<<<BATCH, 256>>>(out);
}

// round 6
// speedup vs baseline: 2.1508x; 2.1508x over previous
#include <cuda_runtime.h>
#include <cstdint>

#define SEQ   2048
#define BATCH 64
#define DIN   128
#define DH    256
#define G3    (3*DH)   // 768

#define NG    16       // batch groups
#define NP    8        // producer blocks (unit tiles) per group
#define BPG   4        // batches per group
#define UPB   32       // hidden units per block
#define ROWSB 96       // 3*UPB gate rows per block
#define HPAD  260

// ---------------- scratch (device globals) ----------------
__device__ float g_gi[(size_t)SEQ * BATCH * G3];
__device__ float g_outs[(size_t)SEQ * BATCH * DH];
__device__ float g_h[2][BATCH * DH];
__device__ float g_scorep[(size_t)SEQ * BATCH * NP];
__device__ float g_scores[SEQ * BATCH];
__device__ float g_wpart[8 * BATCH * DH];
__device__ unsigned int g_flag[NG * NP];    // [m*8+ut] = steps completed

// ---------------- helpers ----------------
__device__ __forceinline__ void fma2(unsigned long long& acc,
                                     unsigned long long a,
                                     unsigned long long b) {
    asm volatile("fma.rn.f32x2 %0, %1, %2, %0;" : "+l"(acc) : "l"(a), "l"(b));
}
__device__ __forceinline__ float2 u2f2(unsigned long long v) {
    float2 f;
    asm("mov.b64 {%0, %1}, %2;" : "=f"(f.x), "=f"(f.y) : "l"(v));
    return f;
}
__device__ __forceinline__ unsigned ld_acq(const unsigned* p) {
    unsigned v;
    asm volatile("ld.global.acquire.gpu.u32 %0, [%1];" : "=r"(v) : "l"(p) : "memory");
    return v;
}
__device__ __forceinline__ void st_rel(unsigned* p, unsigned v) {
    asm volatile("st.global.release.gpu.u32 [%0], %1;" :: "l"(p), "r"(v) : "memory");
}

__global__ void k_init() {
    g_flag[threadIdx.x] = 0u;   // 128 threads
}

// ---------------- Phase 1: GI = mask(data) @ W_ih^T + b_ih ----------------
__global__ void __launch_bounds__(256, 1) gi_gemm(const float* __restrict__ X,
                                                  const float* __restrict__ Wih,
                                                  const float* __restrict__ bih) {
    extern __shared__ float sm[];
    float* As = sm;                // 128 x 132
    float* Bs = sm + 128 * 132;    // 128 x 132
    __shared__ unsigned char maskf[128];

    const int tid = threadIdx.x;
    const int n0 = blockIdx.x * 128;
    const int m0 = blockIdx.y * 128;

    if (tid < 128) maskf[tid] = (X[(size_t)(m0 + tid) * DIN + 127] > 0.0f) ? 1 : 0;
    __syncthreads();

#pragma unroll
    for (int it = 0; it < 16; it++) {
        int t = tid + it * 256;
        int r = t >> 5, kk = t & 31;
        float4 va = *(const float4*)&X[(size_t)(m0 + r) * DIN + kk * 4];
        if (maskf[r] && kk >= 8 && kk < 16) va = make_float4(0.f, 0.f, 0.f, 0.f);
        *(float4*)&As[r * 132 + kk * 4] = va;
        float4 vb = *(const float4*)&Wih[(size_t)(n0 + r) * DIN + kk * 4];
        *(float4*)&Bs[r * 132 + kk * 4] = vb;
    }
    __syncthreads();

    const int tx = tid & 15;
    const int ty = tid >> 4;

    unsigned long long acc[8][8];
#pragma unroll
    for (int i = 0; i < 8; i++)
#pragma unroll
        for (int j = 0; j < 8; j++) acc[i][j] = 0ull;

#pragma unroll 8
    for (int p = 0; p < 64; p++) {
        unsigned long long av[8], bv[8];
#pragma unroll
        for (int i = 0; i < 8; i++)
            av[i] = *(const unsigned long long*)&As[(ty + 16 * i) * 132 + 2 * p];
#pragma unroll
        for (int j = 0; j < 8; j++)
            bv[j] = *(const unsigned long long*)&Bs[(tx + 16 * j) * 132 + 2 * p];
#pragma unroll
        for (int i = 0; i < 8; i++)
#pragma unroll
            for (int j = 0; j < 8; j++) fma2(acc[i][j], av[i], bv[j]);
    }

    __syncthreads();
#pragma unroll
    for (int i = 0; i < 8; i++)
#pragma unroll
        for (int j = 0; j < 8; j++) {
            float2 f = u2f2(acc[i][j]);
            As[(ty + 16 * i) * 132 + tx + 16 * j] = f.x + f.y;
        }
    __syncthreads();

#pragma unroll
    for (int it = 0; it < 16; it++) {
        int t = tid + it * 256;
        int r = t >> 5, kk = t & 31;
        float4 c = *(const float4*)&As[r * 132 + kk * 4];
        float4 b = *(const float4*)&bih[n0 + kk * 4];
        c.x += b.x; c.y += b.y; c.z += b.z; c.w += b.w;
        *(float4*)&g_gi[(size_t)(m0 + r) * G3 + n0 + kk * 4] = c;
    }
}

// ---------------- Phase 2: persistent GRU recurrence ----------------
// 128 blocks = 16 batch-groups x 8 unit-tiles. W_hh in REGISTERS.
// Sync: ONLY warp 0 polls the 8 producer flags (one 32B sector, warp vote),
// __syncthreads gates the block; producers release distinct flag words.
__global__ void __launch_bounds__(256, 1) gru_rec(const float* __restrict__ Whh,
                                                  const float* __restrict__ bhh_g,
                                                  const float* __restrict__ watt) {
    extern __shared__ float sm[];
    float* h_sh = sm;                    // 4 x 260 (full h for this group's 4 batches)
    float* part = sm + BPG * HPAD;       // 384 x 9

    const int tid = threadIdx.x;
    const int ut  = blockIdx.x & 7;      // unit tile 0..7
    const int m   = blockIdx.x >> 3;     // group 0..15

    const int kc = tid >> 4;             // 0..15 k-chunk
    const int rq = tid & 15;             // row group
    const int kbase = kc * 16;

    // epilogue identity (tid < 128)
    const int eb = tid >> 5;             // batch 0..3
    const int eu = tid & 31;             // unit 0..31
    const int ug = ut * UPB + eu;
    const int bg = m * BPG + eb;

    // ---- W_hh tile into registers: 6 rows (rq+16j) x 16 k (kc chunk) ----
    ulonglong2 Wr[6][4];
#pragma unroll
    for (int j = 0; j < 6; j++) {
        const int r = rq + 16 * j;                  // local row 0..95
        const int g = r >> 5, uu = r & 31;
        const float* src = &Whh[(size_t)(g * DH + ut * UPB + uu) * DH + kbase];
#pragma unroll
        for (int q = 0; q < 4; q++)
            Wr[j][q] = *(const ulonglong2*)&src[q * 4];
    }

    float bhh0 = 0.f, bhh1 = 0.f, bhh2 = 0.f, wattv = 0.f;
    if (tid < 128) {
        bhh0 = bhh_g[0 * DH + ug];
        bhh1 = bhh_g[1 * DH + ug];
        bhh2 = bhh_g[2 * DH + ug];
        wattv = watt[ug];
    }

    // staging identity: thread stages one float4 of h
    const int sb = tid >> 6;             // batch 0..3
    const int sf = tid & 63;             // float4 index (k = sf*4)
    const unsigned* pollp = &g_flag[m * NP + (tid & 7)];   // warp0 lanes cover all 8

    for (int s = 0; s < SEQ; s++) {
        // prefetch gi (independent of h) — issued before the wait
        float gir = 0.f, giz = 0.f, gin = 0.f;
        if (tid < 128) {
            const size_t base = ((size_t)s * BATCH + bg) * G3 + ug;
            gir = __ldcg(&g_gi[base]);
            giz = __ldcg(&g_gi[base + DH]);
            gin = __ldcg(&g_gi[base + 2 * DH]);
        }

        if (s > 0) {
            // ONLY warp 0 polls: lane i watches flag (i&7); single 32B sector
            if (tid < 32) {
                const unsigned tgt = (unsigned)s;
                unsigned v;
                do { v = ld_acq(pollp); } while (!__all_sync(0xffffffffu, v >= tgt));
            }
            __syncthreads();   // broadcast: h(s-1) visible to whole block
            float4 hv = __ldcg((const float4*)&g_h[(s - 1) & 1][(m * BPG + sb) * DH + sf * 4]);
            *(float4*)&h_sh[sb * HPAD + sf * 4] = hv;
        } else {
            *(float4*)&h_sh[sb * HPAD + sf * 4] = make_float4(0.f, 0.f, 0.f, 0.f);
        }
        __syncthreads();

        // dots: 4 batches x 6 rows x 16 k, W in regs, h broadcast LDS
        unsigned long long acc[4][6];
#pragma unroll
        for (int i = 0; i < 4; i++)
#pragma unroll
            for (int j = 0; j < 6; j++) acc[i][j] = 0ull;

#pragma unroll
        for (int q = 0; q < 4; q++) {
            ulonglong2 hq[4];
#pragma unroll
            for (int i = 0; i < 4; i++)
                hq[i] = *(const ulonglong2*)&h_sh[i * HPAD + kbase + q * 4];
#pragma unroll
            for (int i = 0; i < 4; i++)
#pragma unroll
                for (int j = 0; j < 6; j++) {
                    fma2(acc[i][j], hq[i].x, Wr[j][q].x);
                    fma2(acc[i][j], hq[i].y, Wr[j][q].y);
                }
        }

        // kc-pair shuffle pre-reduce, then STS (kc-even half-warps)
#pragma unroll
        for (int i = 0; i < 4; i++)
#pragma unroll
            for (int j = 0; j < 6; j++) {
                float2 f = u2f2(acc[i][j]);
                float v = f.x + f.y;
                v += __shfl_xor_sync(0xffffffffu, v, 16);
                if ((tid & 16) == 0)
                    part[(i * ROWSB + rq + 16 * j) * 9 + (kc >> 1)] = v;
            }
        __syncthreads();

        float hnew = 0.f;
        if (tid < 128) {
            float Ar = bhh0 + gir, Az = bhh1 + giz, An = bhh2;
            const int o_r = (eb * ROWSB + eu) * 9;
            const int o_z = (eb * ROWSB + UPB + eu) * 9;
            const int o_n = (eb * ROWSB + 2 * UPB + eu) * 9;
#pragma unroll
            for (int c = 0; c < 8; c++) {
                Ar += part[o_r + c];
                Az += part[o_z + c];
                An += part[o_n + c];
            }
            const float rr = 1.0f / (1.0f + __expf(-Ar));
            const float zz = 1.0f / (1.0f + __expf(-Az));
            const float nn = tanhf(fmaf(rr, An, gin));
            const float hold = h_sh[eb * HPAD + ug];
            hnew = fmaf(zz, hold - nn, nn);
            __stcg(&g_h[s & 1][bg * DH + ug], hnew);
        }
        __syncthreads();   // h stores issued; part/h_sh reads done

        if (tid == 0) st_rel(&g_flag[m * NP + ut], (unsigned)(s + 1));

        // tail work off the inter-block critical path
        if (tid < 128) {
            g_outs[((size_t)s * BATCH + bg) * DH + ug] = hnew;
            float sc = hnew * wattv;
#pragma unroll
            for (int o = 16; o > 0; o >>= 1) sc += __shfl_xor_sync(0xffffffffu, sc, o);
            if (eu == 0) g_scorep[((size_t)s * BATCH + bg) * NP + ut] = sc;
        }
    }
}

// ---------------- Phase 3: attention ----------------
__global__ void k_scores_red() {
    const int idx = blockIdx.x * 256 + threadIdx.x;
    const float4* p = (const float4*)&g_scorep[(size_t)idx * NP];
    float4 a = p[0], b = p[1];
    g_scores[idx] = (a.x + a.y + a.z + a.w) + (b.x + b.y + b.z + b.w);
}

__global__ void k_softmax() {
    __shared__ float red[256];
    const int b = blockIdx.x, tid = threadIdx.x;
    float mx = -1e30f;
    for (int s = tid; s < SEQ; s += 256) mx = fmaxf(mx, g_scores[s * BATCH + b]);
    red[tid] = mx; __syncthreads();
    for (int o = 128; o > 0; o >>= 1) { if (tid < o) red[tid] = fmaxf(red[tid], red[tid + o]); __syncthreads(); }
    mx = red[0]; __syncthreads();
    float sum = 0.f;
    for (int s = tid; s < SEQ; s += 256) sum += __expf(g_scores[s * BATCH + b] - mx);
    red[tid] = sum; __syncthreads();
    for (int o = 128; o > 0; o >>= 1) { if (tid < o) red[tid] += red[tid + o]; __syncthreads(); }
    const float inv = 1.0f / red[0];
    for (int s = tid; s < SEQ; s += 256)
        g_scores[s * BATCH + b] = __expf(g_scores[s * BATCH + b] - mx) * inv;
}

__global__ void k_wsum1() {
    const int b = blockIdx.x, c = blockIdx.y, h = threadIdx.x;
    float acc = 0.f;
    const int s0 = c * 256;
#pragma unroll 4
    for (int s = s0; s < s0 + 256; s++)
        acc = fmaf(__ldg(&g_scores[s * BATCH + b]),
                   g_outs[((size_t)s * BATCH + b) * DH + h], acc);
    g_wpart[(c * BATCH + b) * DH + h] = acc;
}

__global__ void k_wsum2(float* __restrict__ out) {
    const int b = blockIdx.x, h = threadIdx.x;
    float acc = 0.f;
#pragma unroll
    for (int c = 0; c < 8; c++) acc += g_wpart[(c * BATCH + b) * DH + h];
    out[b * DH + h] = acc;
}

// ---------------- launch ----------------
extern "C" void kernel_launch(void* const* d_in, const int* in_sizes, int n_in,
                              void* d_out, int out_size) {
    const float* data = (const float*)d_in[0];
    const float* Wih  = (const float*)d_in[1];
    const float* Whh  = (const float*)d_in[2];
    const float* bih  = (const float*)d_in[3];
    const float* bhh  = (const float*)d_in[4];
    const float* watt = (const float*)d_in[5];
    float* out = (float*)d_out;

    const int gi_smem  = 2 * 128 * 132 * (int)sizeof(float);            // 135168
    const int gru_smem = (BPG * HPAD + 384 * 9) * (int)sizeof(float);   // 17984

    cudaFuncSetAttribute(gi_gemm, cudaFuncAttributeMaxDynamicSharedMemorySize, gi_smem);
    cudaFuncSetAttribute(gru_rec, cudaFuncAttributeMaxDynamicSharedMemorySize, gru_smem);

    k_init<<<1, 128>>>();
    dim3 gg(G3 / 128, (SEQ * BATCH) / 128);   // (6, 1024)
    gi_gemm<<<gg, 256, gi_smem>>>(data, Wih, bih);
    gru_rec<<<NG * NP, 256, gru_smem>>>(Whh, bhh, watt);
    k_scores_red<<<(SEQ * BATCH) / 256, 256>>>();
    k_softmax<<<BATCH, 256>>>();
    dim3 gw(BATCH, 8);
    k_wsum1<<<gw, 256>>>();
    k_wsum2<<<BATCH, 256>>>(out);
}